// round 1
// baseline (speedup 1.0000x reference)
#include <cuda_runtime.h>

// DCT compression: per 8x8 block 2D DCT (cos basis with PI=3.1415), diagonal
// norm, zigzag channel scatter, 1/Q quant scale. Single fused kernel.
//
// Input : x (32, 3, 512, 512) f32
// Output: (32, 192, 64, 64) f32, out[b, c*64 + z(a,u), hb, wb]

#define PI_A 3.1415f

__constant__ float c_TL[64] = {
    16,11,10,16,24,40,51,61,
    12,12,14,19,26,58,60,55,
    14,13,16,24,40,57,69,56,
    14,17,22,29,51,87,80,62,
    18,22,37,56,68,109,103,77,
    24,35,55,64,81,104,113,92,
    49,64,78,87,103,121,120,101,
    72,92,95,98,112,100,103,99};

__constant__ float c_QC[64] = {
    17,18,24,47,99,99,99,99,
    18,21,26,66,99,99,99,99,
    24,26,56,99,99,99,99,99,
    47,66,99,99,99,99,99,99,
    99,99,99,99,99,99,99,99,
    99,99,99,99,99,99,99,99,
    99,99,99,99,99,99,99,99,
    99,99,99,99,99,99,99,99};

// Closed form of the module's zigzag() p[y][x] (verified against the loop port):
//   for s=x+y<8: p = tri(s+1) - (s odd ? y : x) - 1
//   else       : p = 63 - p[7-y][7-x]
__device__ __forceinline__ int zz_p(int y, int x) {
    int s = x + y;
    if (s < 8) {
        int t = (s + 1) * (s + 2) / 2;
        return (s & 1) ? (t - y - 1) : (t - x - 1);
    }
    int yy = 7 - y, xx = 7 - x;
    int s2 = xx + yy;
    int t = (s2 + 1) * (s2 + 2) / 2;
    return 63 - ((s2 & 1) ? (t - yy - 1) : (t - xx - 1));
}

__global__ void __launch_bounds__(128)
dct_kernel(const float* __restrict__ x, float* __restrict__ out) {
    __shared__ float sM[64];      // sM[freq*8 + spatial] = cos((freq+0.5)*PI_A * spatial/8)
    __shared__ float sScale[64];  // norm(a,u) / Qtable[zigzag(a,u)]
    __shared__ int   sChan[64];   // zigzag channel for coef index a*8+u

    const int  tid  = threadIdx.x;
    const long gid0 = (long)blockIdx.x * 128;
    // gid layout: (((b*3 + c)*64 + hb)*64 + wb); c constant within a CTA (4096 % 128 == 0)
    const int  c    = (int)((gid0 >> 12) % 3);

    if (tid < 64) {
        int fi = tid >> 3, j = tid & 7;
        float ap = ((float)fi + 0.5f) * PI_A;   // matches numpy (t+0.5)*PI in f32
        sM[tid] = cosf(ap * ((float)j * 0.125f));
    } else {
        int i = tid - 64;
        int a = i >> 3, u = i & 7;
        int ch = zz_p(u, a);                    // z = pattern.T => z[a*8+u] = p[u][a]
        sChan[i] = ch;
        float nrm = ((a == 0) || (u == 0)) ? 0.17677669529663687f : 0.25f;
        float q   = (c == 0) ? c_TL[ch] : c_QC[ch];
        sScale[i] = nrm / q;
    }
    __syncthreads();

    const long gid = gid0 + tid;
    const int  wb  = (int)(gid & 63);
    const int  hb  = (int)((gid >> 6) & 63);
    const int  bc  = (int)(gid >> 12);          // b*3 + c

    const float* src = x + (((long)bc * 512 + hb * 8) * 512 + wb * 8);

    // Load full 8x8 block first (MLP = 16 LDG.128 in flight)
    float blk[8][8];
#pragma unroll
    for (int y = 0; y < 8; ++y) {
        float4 p0 = *(const float4*)(src + (long)y * 512);
        float4 p1 = *(const float4*)(src + (long)y * 512 + 4);
        blk[y][0] = p0.x; blk[y][1] = p0.y; blk[y][2] = p0.z; blk[y][3] = p0.w;
        blk[y][4] = p1.x; blk[y][5] = p1.y; blk[y][6] = p1.z; blk[y][7] = p1.w;
    }

    // Stage 1: tmp[a][x] = sum_y M[a][y] * blk[y][x]
    float tmp[8][8];
#pragma unroll
    for (int a = 0; a < 8; ++a) {
#pragma unroll
        for (int xx = 0; xx < 8; ++xx) {
            float acc = sM[a * 8] * blk[0][xx];
#pragma unroll
            for (int y = 1; y < 8; ++y)
                acc = fmaf(sM[a * 8 + y], blk[y][xx], acc);
            tmp[a][xx] = acc;
        }
    }

    // Stage 2: coef[a][u] = sum_x tmp[a][x] * M[u][x]; scale; zigzag scatter store.
    // out index = (bc*64 + ch)*4096 + hb*64 + wb
    float* dst = out + ((long)bc << 18) + (hb << 6) + wb;
#pragma unroll
    for (int a = 0; a < 8; ++a) {
#pragma unroll
        for (int u = 0; u < 8; ++u) {
            float s = tmp[a][0] * sM[u * 8];
#pragma unroll
            for (int xx = 1; xx < 8; ++xx)
                s = fmaf(tmp[a][xx], sM[u * 8 + xx], s);
            int i = a * 8 + u;
            dst[(long)sChan[i] << 12] = s * sScale[i];
        }
    }
}

extern "C" void kernel_launch(void* const* d_in, const int* in_sizes, int n_in,
                              void* d_out, int out_size) {
    const float* x   = (const float*)d_in[0];
    float*       out = (float*)d_out;
    // 32*3*64*64 = 393216 blocks, 128 threads (blocks) per CTA -> 3072 CTAs
    dct_kernel<<<3072, 128>>>(x, out);
}